// round 16
// baseline (speedup 1.0000x reference)
#include <cuda_runtime.h>
#include <cuda_fp16.h>
#include <cstdint>

// Problem constants
#define PN 4096
#define PTOPK 2
#define PE 8
#define PH 2048
#define PI 1408
#define PNK (PN * PTOPK)   // 8192

// ---------------- device scratch ----------------
__device__ int g_offsets[PE + 1];
__device__ int g_pair_token[PNK];
__device__ int g_pair_slot[PNK];

__device__ __align__(16) __half g_xhi[(size_t)PN * PH];
__device__ __align__(16) __half g_wghi[(size_t)PE * PI * PH];
__device__ __align__(16) __half g_wuhi[(size_t)PE * PI * PH];
__device__ __align__(16) __half g_wdhi[(size_t)PE * PH * PI];
__device__ __align__(16) __half g_hhi[(size_t)PNK * PI];
__device__ __align__(16) __half g_y[(size_t)PNK * PH];

// ---------------- helpers ----------------
__device__ __forceinline__ uint32_t smem_u32(const void* p) {
    return (uint32_t)__cvta_generic_to_shared(p);
}

__device__ __forceinline__ void cpa16(uint32_t dst, const void* src) {
    asm volatile("cp.async.cg.shared.global [%0], [%1], 16;" :: "r"(dst), "l"(src) : "memory");
}
#define CP_COMMIT() asm volatile("cp.async.commit_group;" ::: "memory")
#define CP_WAIT1()  asm volatile("cp.async.wait_group 1;" ::: "memory")

__device__ __forceinline__ void ldsm_x4(uint32_t* r, uint32_t addr) {
    asm volatile("ldmatrix.sync.aligned.m8n8.x4.shared.b16 {%0,%1,%2,%3}, [%4];"
                 : "=r"(r[0]), "=r"(r[1]), "=r"(r[2]), "=r"(r[3]) : "r"(addr) : "memory");
}
// fp16 mma, fp32 accumulate
__device__ __forceinline__ void mma16816(float* c, const uint32_t* a, const uint32_t* b) {
    asm volatile("mma.sync.aligned.m16n8k16.row.col.f32.f16.f16.f32 "
                 "{%0,%1,%2,%3}, {%4,%5,%6,%7}, {%8,%9}, {%0,%1,%2,%3};"
                 : "+f"(c[0]), "+f"(c[1]), "+f"(c[2]), "+f"(c[3])
                 : "r"(a[0]), "r"(a[1]), "r"(a[2]), "r"(a[3]), "r"(b[0]), "r"(b[1])
                 : "memory");
}

__device__ __forceinline__ float silu_f(float g) {
    return g / (1.0f + __expf(-g));
}

// SW128 swizzle: row r (128B pitch), 16B-chunk c (0..7): chunk' = c ^ (r & 7).
#define SWZ128(r, c) ((uint32_t)((r) * 128 + ((((c) ^ ((r) & 7))) << 4)))

// ---------------- routing: ONE single-CTA kernel ----------------
__global__ void k_route(const int* __restrict__ ids) {
    __shared__ int cnt[PE];
    __shared__ int off[PE + 1];
    __shared__ int cur[PE];
    const int tid = threadIdx.x;
    if (tid < PE) { cnt[tid] = 0; cur[tid] = 0; }
    __syncthreads();
    for (int i = tid; i < PNK; i += 256) atomicAdd(&cnt[ids[i]], 1);
    __syncthreads();
    if (tid == 0) {
        int s = 0;
        for (int e = 0; e < PE; e++) { off[e] = s; g_offsets[e] = s; s += cnt[e]; }
        off[PE] = s;
        g_offsets[PE] = s;
    }
    __syncthreads();
    for (int i = tid; i < PNK; i += 256) {
        int e = ids[i];
        int pos = off[e] + atomicAdd(&cur[e], 1);
        g_pair_token[pos] = i / PTOPK;
        g_pair_slot[i] = pos;
    }
}

// ---------------- fp32 -> fp16 rounding ----------------
// Destination globals referenced from DEVICE code only (host-shadow pitfall).
__device__ __forceinline__ void round_elem(const float* __restrict__ src,
                                           __half* __restrict__ hi, int i) {
    float4 v = reinterpret_cast<const float4*>(src)[i];
    __half2 h0, h1;
    h0.x = __float2half_rn(v.x);
    h0.y = __float2half_rn(v.y);
    h1.x = __float2half_rn(v.z);
    h1.y = __float2half_rn(v.w);
    reinterpret_cast<__half2*>(hi)[i * 2 + 0] = h0;
    reinterpret_cast<__half2*>(hi)[i * 2 + 1] = h1;
}

__global__ void k_split_x(const float* __restrict__ src) {
    const int n4 = PN * PH / 4;
    int i = blockIdx.x * blockDim.x + threadIdx.x;
    int stride = gridDim.x * blockDim.x;
    for (; i < n4; i += stride) round_elem(src, g_xhi, i);
}
// all three weight tensors have identical element counts (E*I*H == E*H*I)
__global__ void k_split_w(const float* __restrict__ wg, const float* __restrict__ wu,
                          const float* __restrict__ wd) {
    const int n4 = PE * PI * PH / 4;
    int i = blockIdx.x * blockDim.x + threadIdx.x;
    int stride = gridDim.x * blockDim.x;
    for (; i < n4; i += stride) {
        round_elem(wg, g_wghi, i);
        round_elem(wu, g_wuhi, i);
        round_elem(wd, g_wdhi, i);
    }
}

// ============================================================================
// GU kernel: single-term fp16 mma.sync, 128 slots x (64 gate + 64 up), BK=64.
// 3-stage cp.async pipeline, SW128 swizzle (128B rows), one barrier per chunk.
// Stage (32768 B): A @0 (16K), Bg @16384 (8K), Bu @24576 (8K).
// ============================================================================
#define GU_STAGE 32768
#define GU_SMEM  (3 * GU_STAGE + 512)

__device__ __forceinline__ void gu_load_stage(uint32_t sb, const int* s_tok, size_t eoff,
                                              int n0, int k0, int tid) {
#pragma unroll
    for (int it = 0; it < 4; it++) {
        int idx = tid + it * 256;          // 0..1023 : A (128 rows x 8 chunks)
        int r = idx >> 3;
        int c = idx & 7;
        const __half* src = g_xhi + (size_t)s_tok[r] * PH + k0 + c * 8;
        cpa16(sb + SWZ128(r, c), src);
    }
#pragma unroll
    for (int it = 0; it < 4; it++) {
        int idx = tid + it * 256;          // 0..1023 : Bg, Bu (2 x 64 rows x 8)
        int t = idx >> 9;                  // 0..1
        int r = (idx >> 3) & 63;
        int c = idx & 7;
        const __half* base = t ? g_wuhi : g_wghi;
        const __half* src = base + eoff + (size_t)(n0 + r) * PH + k0 + c * 8;
        cpa16(sb + 16384 + t * 8192 + SWZ128(r, c), src);
    }
}

__global__ __launch_bounds__(256, 2) void k_gu() {
    extern __shared__ __align__(128) char smem[];
    const int e = blockIdx.z;
    const int beg = g_offsets[e];
    const int end = g_offsets[e + 1];
    const int row0 = beg + blockIdx.x * 128;
    if (row0 >= end) return;
    const int n0 = blockIdx.y * 64;

    const int tid = threadIdx.x;
    const int wid = tid >> 5;
    const int lane = tid & 31;
    const int wr = wid >> 1;   // rows wr*32..+31
    const int wc = wid & 1;    // cols wc*32..+31

    int* s_tok = reinterpret_cast<int*>(smem + 3 * GU_STAGE);
    if (tid < 128) {
        int slot = row0 + tid;
        if (slot >= PNK) slot = PNK - 1;
        s_tok[tid] = g_pair_token[slot];
    }
    __syncthreads();

    const size_t eoff = (size_t)e * PI * PH;

    float accg[2][4][4];
    float accu[2][4][4];
#pragma unroll
    for (int mi = 0; mi < 2; mi++)
#pragma unroll
        for (int ni = 0; ni < 4; ni++)
#pragma unroll
            for (int q = 0; q < 4; q++) { accg[mi][ni][q] = 0.0f; accu[mi][ni][q] = 0.0f; }

    const uint32_t sb0 = smem_u32(smem);

    const int rA = wr * 32 + (lane & 15);
    const uint32_t aRow0 = (uint32_t)rA * 128;
    const int aC = lane >> 4;
    const int x7 = lane & 7;
    const int rBl = (lane & 7) + 8 * ((lane >> 4) & 1);
    const uint32_t bRow0 = (uint32_t)(wc * 32 + rBl) * 128;
    const int bC = (lane >> 3) & 1;

    gu_load_stage(sb0, s_tok, eoff, n0, 0, tid);
    CP_COMMIT();
    gu_load_stage(sb0 + GU_STAGE, s_tok, eoff, n0, 64, tid);
    CP_COMMIT();

    const int NC = PH / 64;  // 32
    int cb = 0, lb = 2;
    for (int c = 0; c < NC; c++) {
        CP_WAIT1();
        __syncthreads();
        if (c + 2 < NC)
            gu_load_stage(sb0 + lb * GU_STAGE, s_tok, eoff, n0, (c + 2) * 64, tid);
        CP_COMMIT();

        const uint32_t sbA = sb0 + cb * GU_STAGE;
        const uint32_t sbBg = sbA + 16384;
        const uint32_t sbBu = sbA + 24576;
#pragma unroll
        for (int ks = 0; ks < 4; ks++) {
            const uint32_t tA = (uint32_t)(((aC + 2 * ks) ^ x7) << 4);
            const uint32_t tB = (uint32_t)(((bC + 2 * ks) ^ x7) << 4);
            uint32_t ahi[2][4];
            ldsm_x4(ahi[0], sbA + aRow0 + tA);
            ldsm_x4(ahi[1], sbA + aRow0 + 2048 + tA);
            {   // gate
                uint32_t bh[8];
                ldsm_x4(bh + 0, sbBg + bRow0 + tB);
                ldsm_x4(bh + 4, sbBg + bRow0 + 2048 + tB);
#pragma unroll
                for (int ni = 0; ni < 4; ni++) {
                    const uint32_t* ph = &bh[(ni >> 1) * 4 + (ni & 1) * 2];
#pragma unroll
                    for (int mi = 0; mi < 2; mi++)
                        mma16816(accg[mi][ni], ahi[mi], ph);
                }
            }
            {   // up
                uint32_t bh[8];
                ldsm_x4(bh + 0, sbBu + bRow0 + tB);
                ldsm_x4(bh + 4, sbBu + bRow0 + 2048 + tB);
#pragma unroll
                for (int ni = 0; ni < 4; ni++) {
                    const uint32_t* ph = &bh[(ni >> 1) * 4 + (ni & 1) * 2];
#pragma unroll
                    for (int mi = 0; mi < 2; mi++)
                        mma16816(accu[mi][ni], ahi[mi], ph);
                }
            }
        }
        cb = (cb == 2) ? 0 : cb + 1;
        lb = (lb == 2) ? 0 : lb + 1;
    }

    // epilogue: h = silu(g)*u -> fp16
    const int gRow = lane >> 2;
    const int cp2 = (lane & 3) * 2;
#pragma unroll
    for (int mi = 0; mi < 2; mi++) {
#pragma unroll
        for (int ni = 0; ni < 4; ni++) {
            int col = n0 + wc * 32 + ni * 8 + cp2;
            int r0 = wr * 32 + mi * 16 + gRow;
#pragma unroll
            for (int half_i = 0; half_i < 2; half_i++) {
                int slot = row0 + r0 + half_i * 8;
                if (slot < end) {
                    float g0 = accg[mi][ni][half_i * 2 + 0];
                    float g1 = accg[mi][ni][half_i * 2 + 1];
                    float u0 = accu[mi][ni][half_i * 2 + 0];
                    float u1 = accu[mi][ni][half_i * 2 + 1];
                    __half2 vh;
                    vh.x = __float2half_rn(silu_f(g0) * u0);
                    vh.y = __float2half_rn(silu_f(g1) * u1);
                    *reinterpret_cast<__half2*>(g_hhi + (size_t)slot * PI + col) = vh;
                }
            }
        }
    }
}

// ============================================================================
// Down kernel: single-term fp16, 128 slots x 128 H-cols, BK=64 over I.
// Stage (32768 B): A @0 (16K), B @16384 (16K). Writes fp16 y.
// ============================================================================
#define D_STAGE 32768
#define D_SMEM  (3 * D_STAGE + 512)

__device__ __forceinline__ void d_load_stage(uint32_t sb, int row0, size_t eoff,
                                             int n0, int k0, int tid) {
#pragma unroll
    for (int it = 0; it < 4; it++) {
        int idx = tid + it * 256;          // A (128 rows x 8 chunks)
        int r = idx >> 3;
        int c = idx & 7;
        int slot = row0 + r;
        if (slot >= PNK) slot = PNK - 1;
        const __half* src = g_hhi + (size_t)slot * PI + k0 + c * 8;
        cpa16(sb + SWZ128(r, c), src);
    }
#pragma unroll
    for (int it = 0; it < 4; it++) {
        int idx = tid + it * 256;          // B (128 rows x 8 chunks)
        int r = idx >> 3;
        int c = idx & 7;
        const __half* src = g_wdhi + eoff + (size_t)(n0 + r) * PI + k0 + c * 8;
        cpa16(sb + 16384 + SWZ128(r, c), src);
    }
}

__global__ __launch_bounds__(256, 2) void k_down() {
    extern __shared__ __align__(128) char smem[];
    const int e = blockIdx.z;
    const int beg = g_offsets[e];
    const int end = g_offsets[e + 1];
    const int row0 = beg + blockIdx.x * 128;
    if (row0 >= end) return;
    const int n0 = blockIdx.y * 128;

    const int tid = threadIdx.x;
    const int wid = tid >> 5;
    const int lane = tid & 31;
    const int wr = wid >> 1;   // rows wr*32..+31
    const int wc = wid & 1;    // cols wc*64..+63

    const size_t eoff = (size_t)e * PH * PI;

    float acc[2][8][4];
#pragma unroll
    for (int mi = 0; mi < 2; mi++)
#pragma unroll
        for (int ni = 0; ni < 8; ni++)
#pragma unroll
            for (int q = 0; q < 4; q++) acc[mi][ni][q] = 0.0f;

    const uint32_t sb0 = smem_u32(smem);

    const int rA = wr * 32 + (lane & 15);
    const uint32_t aRow0 = (uint32_t)rA * 128;
    const int aC = lane >> 4;
    const int x7 = lane & 7;
    const int rBl = (lane & 7) + 8 * ((lane >> 4) & 1);
    const uint32_t bRow0 = (uint32_t)(wc * 64 + rBl) * 128;
    const int bC = (lane >> 3) & 1;

    d_load_stage(sb0, row0, eoff, n0, 0, tid);
    CP_COMMIT();
    d_load_stage(sb0 + D_STAGE, row0, eoff, n0, 64, tid);
    CP_COMMIT();

    const int NC = PI / 64;  // 22
    int cb = 0, lb = 2;
    for (int c = 0; c < NC; c++) {
        CP_WAIT1();
        __syncthreads();
        if (c + 2 < NC)
            d_load_stage(sb0 + lb * D_STAGE, row0, eoff, n0, (c + 2) * 64, tid);
        CP_COMMIT();

        const uint32_t sbA = sb0 + cb * D_STAGE;
        const uint32_t sbB = sbA + 16384;
#pragma unroll
        for (int ks = 0; ks < 4; ks++) {
            const uint32_t tA = (uint32_t)(((aC + 2 * ks) ^ x7) << 4);
            const uint32_t tB = (uint32_t)(((bC + 2 * ks) ^ x7) << 4);
            uint32_t ahi[2][4];
            ldsm_x4(ahi[0], sbA + aRow0 + tA);
            ldsm_x4(ahi[1], sbA + aRow0 + 2048 + tA);
            // batch B loads in pairs of h -> longer mma bursts (16 mma per burst)
#pragma unroll
            for (int hp = 0; hp < 2; hp++) {
                uint32_t bh[8];
                ldsm_x4(bh + 0, sbB + bRow0 + (hp * 2 + 0) * 2048 + tB);
                ldsm_x4(bh + 4, sbB + bRow0 + (hp * 2 + 1) * 2048 + tB);
#pragma unroll
                for (int q = 0; q < 4; q++) {
                    int ni = hp * 4 + q;
                    const uint32_t* ph = &bh[((q >> 1) * 4) + (q & 1) * 2];
#pragma unroll
                    for (int mi = 0; mi < 2; mi++)
                        mma16816(acc[mi][ni], ahi[mi], ph);
                }
            }
        }
        cb = (cb == 2) ? 0 : cb + 1;
        lb = (lb == 2) ? 0 : lb + 1;
    }

    // epilogue: y[slot][col] = fp16(acc)
    const int gRow = lane >> 2;
    const int cp2 = (lane & 3) * 2;
#pragma unroll
    for (int mi = 0; mi < 2; mi++) {
#pragma unroll
        for (int ni = 0; ni < 8; ni++) {
            int col = n0 + wc * 64 + ni * 8 + cp2;
            int r0 = wr * 32 + mi * 16 + gRow;
#pragma unroll
            for (int half_i = 0; half_i < 2; half_i++) {
                int lr = r0 + half_i * 8;
                int slot = row0 + lr;
                if (slot < end) {
                    __half2 v;
                    v.x = __float2half_rn(acc[mi][ni][half_i * 2 + 0]);
                    v.y = __float2half_rn(acc[mi][ni][half_i * 2 + 1]);
                    *reinterpret_cast<__half2*>(g_y + (size_t)slot * PH + col) = v;
                }
            }
        }
    }
}

// ---------------- combine: out[n] = w0*y[slot0] + w1*y[slot1] ----------------
__global__ void k_combine(const float* __restrict__ tw, float* __restrict__ out) {
    int idx = blockIdx.x * blockDim.x + threadIdx.x;  // over PN * (PH/4)
    if (idx >= PN * (PH / 4)) return;
    int n = idx / (PH / 4);
    int hq = idx % (PH / 4);
    int s0 = g_pair_slot[n * 2 + 0];
    int s1 = g_pair_slot[n * 2 + 1];
    float w0 = tw[n * 2 + 0];
    float w1 = tw[n * 2 + 1];
    const __half2* pa = reinterpret_cast<const __half2*>(g_y + (size_t)s0 * PH + hq * 4);
    const __half2* pb = reinterpret_cast<const __half2*>(g_y + (size_t)s1 * PH + hq * 4);
    __half2 a0 = pa[0], a1 = pa[1];
    __half2 b0 = pb[0], b1 = pb[1];
    float4 o;
    o.x = w0 * __half2float(a0.x) + w1 * __half2float(b0.x);
    o.y = w0 * __half2float(a0.y) + w1 * __half2float(b0.y);
    o.z = w0 * __half2float(a1.x) + w1 * __half2float(b1.x);
    o.w = w0 * __half2float(a1.y) + w1 * __half2float(b1.y);
    *reinterpret_cast<float4*>(out + (size_t)n * PH + hq * 4) = o;
}

// ---------------- launch ----------------
extern "C" void kernel_launch(void* const* d_in, const int* in_sizes, int n_in,
                              void* d_out, int out_size) {
    const float* x = (const float*)d_in[0];          // [N, H]
    const int* topk_ids = (const int*)d_in[1];       // [N, K]
    const float* topk_w = (const float*)d_in[2];     // [N, K]
    const float* Wg = (const float*)d_in[3];         // [E, I, H]
    const float* Wu = (const float*)d_in[4];         // [E, I, H]
    const float* Wd = (const float*)d_in[5];         // [E, H, I]
    float* out = (float*)d_out;                      // [N, H]

    static bool attr_done = false;
    if (!attr_done) {
        cudaFuncSetAttribute(k_gu, cudaFuncAttributeMaxDynamicSharedMemorySize, GU_SMEM);
        cudaFuncSetAttribute(k_down, cudaFuncAttributeMaxDynamicSharedMemorySize, D_SMEM);
        attr_done = true;
    }

    // launch index 0..2
    k_route<<<1, 256>>>(topk_ids);
    k_split_x<<<4096, 256>>>(x);
    k_split_w<<<8192, 256>>>(Wg, Wu, Wd);
    // launch index 3 == k_gu (ncu capture lands on the 4th launch)
    {
        dim3 grid(PN / 128, PI / 64, PE);    // 32 x 22 x 8
        k_gu<<<grid, 256, GU_SMEM>>>();
    }
    // launch index 4
    {
        dim3 grid(PN / 128, PH / 128, PE);   // 32 x 16 x 8
        k_down<<<grid, 256, D_SMEM>>>();
    }
    // launch index 5
    k_combine<<<(PN * (PH / 4) + 255) / 256, 256>>>(topk_w, out);
}